// round 9
// baseline (speedup 1.0000x reference)
#include <cuda_runtime.h>

#define NN 100000
#define EE 1600000
#define HH 64
#define GG 512
#define FULL 0xffffffffu
#define TILE_N 128
#define ASTRIDE 136
#define NB 98              // ceil(NN / 1024)

// ---------------- device scratch ----------------
__device__ int   d_deg_in[NN];
__device__ int   d_deg_out[NN];
__device__ int   d_rowptr[NN + 1];
__device__ int   d_colptr[NN + 1];
__device__ int   d_rowcur[NN];
__device__ int   d_colcur[NN];
__device__ int   d_rowedges[EE];   // edge ids grouped by source
__device__ int   d_colsrc[EE];     // source node ids grouped by target
__device__ float d_dinv[NN];
__device__ float d_A[NN * 32];     // aggregated edge_attr per source node
__device__ float d_h[NN * HH];     // node features (agg output / gemm input)
__device__ float d_g[NN * HH];     // gemm output, pre-scaled by dinv[n]
__device__ int   d_part[2 * NB];   // per-chunk degree sums
__device__ int   d_partx[2 * NB];  // exclusive-scanned chunk offsets
// folded layer-1 weights: W @ Wg1
__device__ float d_Wn1[128 * 64];
__device__ float d_We1[32 * 64];
__device__ float d_bn1[64];
__device__ float d_be1[64];

#define FMA4(ACC, AV, B) \
    ACC.x = fmaf(AV, B.x, ACC.x); ACC.y = fmaf(AV, B.y, ACC.y); \
    ACC.z = fmaf(AV, B.z, ACC.z); ACC.w = fmaf(AV, B.w, ACC.w)

// ---------------- fold: [Wn;We;bn;be] @ Wg1 (162 rows x 64) ----------------
__global__ void k_fold(const float* __restrict__ Wn, const float* __restrict__ We,
                       const float* __restrict__ bn, const float* __restrict__ be,
                       const float* __restrict__ Wg1) {
    __shared__ float sW[64 * 64];
    int t = threadIdx.x;  // 64 threads
    for (int i = t; i < 64 * 64; i += 64) sW[i] = Wg1[i];
    __syncthreads();
    int row = blockIdx.x;  // 0..161
    const float* src;
    float* dst;
    if (row < 128)      { src = &Wn[row * 64];          dst = &d_Wn1[row * 64]; }
    else if (row < 160) { src = &We[(row - 128) * 64];  dst = &d_We1[(row - 128) * 64]; }
    else if (row == 160){ src = bn;                     dst = d_bn1; }
    else                { src = be;                     dst = d_be1; }
    float acc = 0.0f;
#pragma unroll 16
    for (int k = 0; k < 64; k++) acc = fmaf(src[k], sW[k * 64 + t], acc);
    dst[t] = acc;
}

// ---------------- degree histograms ----------------
__global__ void k_zero() {
    int i = blockIdx.x * blockDim.x + threadIdx.x;
    int s = gridDim.x * blockDim.x;
    for (; i < NN; i += s) { d_deg_in[i] = 0; d_deg_out[i] = 0; }
}

__global__ void k_count(const int* __restrict__ ei) {
    int i = blockIdx.x * blockDim.x + threadIdx.x;
    int s = gridDim.x * blockDim.x;
    for (; i < EE; i += s) {
        atomicAdd(&d_deg_out[ei[i]], 1);
        atomicAdd(&d_deg_in[ei[EE + i]], 1);
    }
}

// ===== 3-phase device-wide exclusive scan of both degree arrays ==============
__global__ void k_scanpart() {
    __shared__ int red[256];
    int b = blockIdx.x;
    const int* deg = (b < NB) ? d_deg_out : d_deg_in;
    int cb = (b < NB) ? b : b - NB;
    int base = cb * 1024 + threadIdx.x * 4;
    int s = 0;
#pragma unroll
    for (int i = 0; i < 4; i++) {
        int idx = base + i;
        if (idx < NN) s += deg[idx];
    }
    red[threadIdx.x] = s;
    __syncthreads();
    for (int off = 128; off; off >>= 1) {
        if (threadIdx.x < off) red[threadIdx.x] += red[threadIdx.x + off];
        __syncthreads();
    }
    if (threadIdx.x == 0) d_part[b] = red[0];
}

__global__ void k_scanmid() {
    __shared__ int sc[128];
    int a = blockIdx.x;            // 0 = row, 1 = col
    int t = threadIdx.x;
    int v = (t < NB) ? d_part[a * NB + t] : 0;
    sc[t] = v;
    __syncthreads();
    for (int off = 1; off < 128; off <<= 1) {
        int u = (t >= off) ? sc[t - off] : 0;
        __syncthreads();
        sc[t] += u;
        __syncthreads();
    }
    if (t < NB) d_partx[a * NB + t] = sc[t] - v;   // exclusive
    if (t == NB - 1) {
        if (a == 0) d_rowptr[NN] = sc[t];
        else        d_colptr[NN] = sc[t];
    }
}

__global__ void k_writeptr() {
    __shared__ int sc[1024];
    int b = blockIdx.x;
    int is_col = (b >= NB);
    const int* deg = is_col ? d_deg_in : d_deg_out;
    int* ptr = is_col ? d_colptr : d_rowptr;
    int* cur = is_col ? d_colcur : d_rowcur;
    int cb = is_col ? b - NB : b;
    int t = threadIdx.x;
    int i = cb * 1024 + t;
    int v = (i < NN) ? deg[i] : 0;
    sc[t] = v;
    __syncthreads();
    for (int off = 1; off < 1024; off <<= 1) {
        int u = (t >= off) ? sc[t - off] : 0;
        __syncthreads();
        sc[t] += u;
        __syncthreads();
    }
    if (i < NN) {
        int excl = sc[t] - v + d_partx[b];
        ptr[i] = excl;
        cur[i] = excl;
        if (is_col) d_dinv[i] = rsqrtf((float)(v + 1));
    }
}

__global__ void k_scatter(const int* __restrict__ ei) {
    int i = blockIdx.x * blockDim.x + threadIdx.x;
    int s = gridDim.x * blockDim.x;
    for (; i < EE; i += s) {
        int r = ei[i];
        int c = ei[EE + i];
        d_rowedges[atomicAdd(&d_rowcur[r], 1)] = i;
        d_colsrc[atomicAdd(&d_colcur[c], 1)] = r;
    }
}

// ------ A[n] = sum_{e: src=n} edge_attr[e]; 4 edges/warp-iter, float4 lanes ---
__global__ void k_aggattr(const float* __restrict__ ea) {
    int n = blockIdx.x * 8 + (threadIdx.x >> 5);
    int lane = threadIdx.x & 31;
    int grp = lane >> 3;        // 0..3: which edge of the 4-pack
    int gl  = lane & 7;         // 0..7: float4 column slot
    if (n >= NN) return;
    int beg = d_rowptr[n], end = d_rowptr[n + 1];
    float4 acc = make_float4(0.f, 0.f, 0.f, 0.f);
    for (int base = beg; base < end; base += 32) {
        int ev = (base + lane < end) ? d_rowedges[base + lane] : -1;
#pragma unroll
        for (int t = 0; t < 8; t++) {
            int e = __shfl_sync(FULL, ev, t * 4 + grp);
            if (e >= 0) {
                float4 v = *(const float4*)&ea[e * 32 + gl * 4];
                acc.x += v.x; acc.y += v.y; acc.z += v.z; acc.w += v.w;
            }
        }
    }
    // combine the 4 edge-groups (lanes with same gl)
#pragma unroll
    for (int off = 8; off <= 16; off <<= 1) {
        acc.x += __shfl_xor_sync(FULL, acc.x, off);
        acc.y += __shfl_xor_sync(FULL, acc.y, off);
        acc.z += __shfl_xor_sync(FULL, acc.z, off);
        acc.w += __shfl_xor_sync(FULL, acc.w, off);
    }
    if (lane < 8) *(float4*)&d_A[n * 32 + gl * 4] = acc;
}

// === tiled SGEMM (layer-1 folded): g = dinv * (x@Wn1 + A@We1 + bn1 + deg*be1)
__global__ void k_gemm1(const float* __restrict__ x) {
    __shared__ float sA[32 * ASTRIDE];
    __shared__ float sB[32 * 64];
    int t = threadIdx.x;
    int nb = blockIdx.x * TILE_N;
    int tx = t >> 4, ty = t & 15;       // node group / col group
    int ln = t >> 1;                    // loader node 0..127
    int kh = (t & 1) * 16;              // loader k-offset
    int gn = nb + ln;

    float4 acc[8];
#pragma unroll
    for (int i = 0; i < 8; i++) acc[i] = make_float4(0.f, 0.f, 0.f, 0.f);

    for (int c = 0; c < 5; c++) {
        __syncthreads();
        const float4* Wv = (c < 4) ? (const float4*)(d_Wn1 + c * 2048)
                                   : (const float4*)d_We1;
        ((float4*)sB)[t]       = Wv[t];
        ((float4*)sB)[t + 256] = Wv[t + 256];

        float4 v[4];
#pragma unroll
        for (int i = 0; i < 4; i++) {
            if (gn < NN) {
                v[i] = (c < 4) ? *(const float4*)&x[gn * 128 + c * 32 + kh + 4 * i]
                               : *(const float4*)&d_A[gn * 32 + kh + 4 * i];
            } else v[i] = make_float4(0.f, 0.f, 0.f, 0.f);
        }
#pragma unroll
        for (int i = 0; i < 4; i++) {
            sA[(kh + 4 * i + 0) * ASTRIDE + ln] = v[i].x;
            sA[(kh + 4 * i + 1) * ASTRIDE + ln] = v[i].y;
            sA[(kh + 4 * i + 2) * ASTRIDE + ln] = v[i].z;
            sA[(kh + 4 * i + 3) * ASTRIDE + ln] = v[i].w;
        }
        __syncthreads();
#pragma unroll 8
        for (int k = 0; k < 32; k++) {
            float4 a0 = *(const float4*)&sA[k * ASTRIDE + tx * 8];
            float4 a1 = *(const float4*)&sA[k * ASTRIDE + tx * 8 + 4];
            float4 b  = *(const float4*)&sB[k * 64 + ty * 4];
            FMA4(acc[0], a0.x, b); FMA4(acc[1], a0.y, b);
            FMA4(acc[2], a0.z, b); FMA4(acc[3], a0.w, b);
            FMA4(acc[4], a1.x, b); FMA4(acc[5], a1.y, b);
            FMA4(acc[6], a1.z, b); FMA4(acc[7], a1.w, b);
        }
    }
    float4 bnv = *(const float4*)&d_bn1[ty * 4];
    float4 bev = *(const float4*)&d_be1[ty * 4];
    int nrow = nb + tx * 8;
#pragma unroll
    for (int i = 0; i < 8; i++) {
        int n = nrow + i;
        if (n < NN) {
            float dg = (float)d_deg_out[n];
            float sc = d_dinv[n];
            float4 o;
            o.x = sc * (acc[i].x + bnv.x + dg * bev.x);
            o.y = sc * (acc[i].y + bnv.y + dg * bev.y);
            o.z = sc * (acc[i].z + bnv.z + dg * bev.z);
            o.w = sc * (acc[i].w + bnv.w + dg * bev.w);
            *(float4*)&d_g[n * 64 + ty * 4] = o;
        }
    }
}

// ====== tiled SGEMM: g[n] = dinv[n] * (h[n] @ W)  (64x64) ====================
__global__ void k_gemm64(const float* __restrict__ W) {
    __shared__ float sA[32 * ASTRIDE];
    __shared__ float sB[32 * 64];
    int t = threadIdx.x;
    int nb = blockIdx.x * TILE_N;
    int tx = t >> 4, ty = t & 15;
    int ln = t >> 1;
    int kh = (t & 1) * 16;
    int gn = nb + ln;

    float4 acc[8];
#pragma unroll
    for (int i = 0; i < 8; i++) acc[i] = make_float4(0.f, 0.f, 0.f, 0.f);

    for (int c = 0; c < 2; c++) {
        __syncthreads();
        const float4* Wv = (const float4*)(W + c * 2048);
        ((float4*)sB)[t]       = Wv[t];
        ((float4*)sB)[t + 256] = Wv[t + 256];

        float4 v[4];
#pragma unroll
        for (int i = 0; i < 4; i++)
            v[i] = (gn < NN) ? *(const float4*)&d_h[gn * 64 + c * 32 + kh + 4 * i]
                             : make_float4(0.f, 0.f, 0.f, 0.f);
#pragma unroll
        for (int i = 0; i < 4; i++) {
            sA[(kh + 4 * i + 0) * ASTRIDE + ln] = v[i].x;
            sA[(kh + 4 * i + 1) * ASTRIDE + ln] = v[i].y;
            sA[(kh + 4 * i + 2) * ASTRIDE + ln] = v[i].z;
            sA[(kh + 4 * i + 3) * ASTRIDE + ln] = v[i].w;
        }
        __syncthreads();
#pragma unroll 8
        for (int k = 0; k < 32; k++) {
            float4 a0 = *(const float4*)&sA[k * ASTRIDE + tx * 8];
            float4 a1 = *(const float4*)&sA[k * ASTRIDE + tx * 8 + 4];
            float4 b  = *(const float4*)&sB[k * 64 + ty * 4];
            FMA4(acc[0], a0.x, b); FMA4(acc[1], a0.y, b);
            FMA4(acc[2], a0.z, b); FMA4(acc[3], a0.w, b);
            FMA4(acc[4], a1.x, b); FMA4(acc[5], a1.y, b);
            FMA4(acc[6], a1.z, b); FMA4(acc[7], a1.w, b);
        }
    }
    int nrow = nb + tx * 8;
#pragma unroll
    for (int i = 0; i < 8; i++) {
        int n = nrow + i;
        if (n < NN) {
            float sc = d_dinv[n];
            float4 o;
            o.x = sc * acc[i].x; o.y = sc * acc[i].y;
            o.z = sc * acc[i].z; o.w = sc * acc[i].w;
            *(float4*)&d_g[n * 64 + ty * 4] = o;
        }
    }
}

// --- h[c] = act( dinv[c]*(sum_{s->c} g[s] + g[c]) + b ); 2 nodes/warp, float4 --
__global__ void k_agg(const float* __restrict__ bias, int do_relu) {
    int warp = threadIdx.x >> 5;
    int lane = threadIdx.x & 31;
    int half = lane >> 4;                // 0 or 1: which node
    int hl   = lane & 15;                // 0..15: float4 column slot
    int n = blockIdx.x * 16 + warp * 2 + half;
    if (n >= NN) return;
    unsigned hmask = half ? 0xFFFF0000u : 0x0000FFFFu;
    int beg = d_colptr[n], end = d_colptr[n + 1];
    float4 acc = *(const float4*)&d_g[n * 64 + hl * 4];  // self loop
    for (int base = beg; base < end; base += 16) {
        int cnt = min(16, end - base);
        int sv = (base + hl < end) ? d_colsrc[base + hl] : 0;
        for (int t = 0; t < cnt; t++) {
            int s = __shfl_sync(hmask, sv, (half << 4) + t);
            float4 v = __ldg((const float4*)&d_g[s * 64 + hl * 4]);
            acc.x += v.x; acc.y += v.y; acc.z += v.z; acc.w += v.w;
        }
    }
    float sc = d_dinv[n];
    float4 b = *(const float4*)&bias[hl * 4];
    float4 o;
    o.x = fmaf(sc, acc.x, b.x);
    o.y = fmaf(sc, acc.y, b.y);
    o.z = fmaf(sc, acc.z, b.z);
    o.w = fmaf(sc, acc.w, b.w);
    if (do_relu) {
        o.x = fmaxf(o.x, 0.0f); o.y = fmaxf(o.y, 0.0f);
        o.z = fmaxf(o.z, 0.0f); o.w = fmaxf(o.w, 0.0f);
    }
    *(float4*)&d_h[n * 64 + hl * 4] = o;
}

// ---------------- mean pool (sorted batch) + classifier ----------------
__device__ __forceinline__ int lbound(const int* a, int n, int v) {
    int lo = 0, hi = n;
    while (lo < hi) {
        int mid = (lo + hi) >> 1;
        if (a[mid] < v) lo = mid + 1; else hi = mid;
    }
    return lo;
}

__global__ void k_classifier(const int* __restrict__ batch,
                             const float* __restrict__ Wc1, const float* __restrict__ bc1,
                             const float* __restrict__ Wc2, const float* __restrict__ bc2,
                             float* __restrict__ out) {
    int g = blockIdx.x * 8 + (threadIdx.x >> 5);
    int lane = threadIdx.x & 31;
    if (g >= GG) return;
    int lo = 0, hi = 0;
    if (lane == 0) {
        lo = lbound(batch, NN, g);
        hi = lbound(batch, NN, g + 1);
    }
    lo = __shfl_sync(FULL, lo, 0);
    hi = __shfl_sync(FULL, hi, 0);
    float2 s = make_float2(0.0f, 0.0f);
    for (int n = lo; n < hi; n++) {
        float2 v = *(const float2*)&d_h[n * 64 + 2 * lane];
        s.x += v.x; s.y += v.y;
    }
    float cnt = (float)(hi - lo);
    float inv = (cnt > 0.0f) ? 1.0f / cnt : 0.0f;
    float m0 = s.x * inv, m1 = s.y * inv;  // cols 2*lane, 2*lane+1
    float hid = bc1[lane];
#pragma unroll
    for (int k = 0; k < 64; k++) {
        float src = (k & 1) ? m1 : m0;
        float mk = __shfl_sync(FULL, src, k >> 1);
        hid = fmaf(mk, Wc1[k * 32 + lane], hid);
    }
    hid = fmaxf(hid, 0.0f);
    float v = hid * Wc2[lane];
#pragma unroll
    for (int off = 16; off; off >>= 1) v += __shfl_xor_sync(FULL, v, off);
    if (lane == 0) out[g] = v + bc2[0];
}

// ---------------- launch ----------------
extern "C" void kernel_launch(void* const* d_in, const int* in_sizes, int n_in,
                              void* d_out, int out_size) {
    const float* x    = (const float*)d_in[0];
    const int*   ei   = (const int*)  d_in[1];
    const float* ea   = (const float*)d_in[2];
    const int*   batch= (const int*)  d_in[3];
    const float* Wn   = (const float*)d_in[4];
    const float* bn   = (const float*)d_in[5];
    const float* We   = (const float*)d_in[6];
    const float* be   = (const float*)d_in[7];
    const float* Wg1  = (const float*)d_in[8];
    const float* bg1  = (const float*)d_in[9];
    const float* Wg2  = (const float*)d_in[10];
    const float* bg2  = (const float*)d_in[11];
    const float* Wg3  = (const float*)d_in[12];
    const float* bg3  = (const float*)d_in[13];
    const float* Wc1  = (const float*)d_in[14];
    const float* bc1  = (const float*)d_in[15];
    const float* Wc2  = (const float*)d_in[16];
    const float* bc2  = (const float*)d_in[17];
    float* out = (float*)d_out;

    const int WB  = (NN + 7) / 8;                  // warp-per-node blocks
    const int AB  = (NN + 15) / 16;                // 2-nodes-per-warp blocks
    const int GB  = (NN + TILE_N - 1) / TILE_N;    // gemm tiles

    k_fold<<<162, 64>>>(Wn, We, bn, be, Wg1);
    k_zero<<<256, 256>>>();
    k_count<<<1024, 256>>>(ei);
    k_scanpart<<<2 * NB, 256>>>();
    k_scanmid<<<2, 128>>>();
    k_writeptr<<<2 * NB, 1024>>>();
    k_scatter<<<1024, 256>>>(ei);
    k_aggattr<<<WB, 256>>>(ea);
    k_gemm1<<<GB, 256>>>(x);                       // emits layer-1 g directly

    k_agg<<<AB, 256>>>(bg1, 1);
    k_gemm64<<<GB, 256>>>(Wg2);
    k_agg<<<AB, 256>>>(bg2, 1);
    k_gemm64<<<GB, 256>>>(Wg3);
    k_agg<<<AB, 256>>>(bg3, 0);

    k_classifier<<<64, 256>>>(batch, Wc1, bc1, Wc2, bc2, out);
}

// round 10
// speedup vs baseline: 1.0358x; 1.0358x over previous
#include <cuda_runtime.h>
#include <cuda_fp16.h>

#define NN 100000
#define EE 1600000
#define HH 64
#define GG 512
#define FULL 0xffffffffu
#define TILE_N 128
#define ASTRIDE 136
#define NB 98              // ceil(NN / 1024)

// ---------------- device scratch ----------------
__device__ int    d_deg_in[NN];
__device__ int    d_deg_out[NN];
__device__ int    d_rowptr[NN + 1];
__device__ int    d_colptr[NN + 1];
__device__ int    d_rowcur[NN];
__device__ int    d_colcur[NN];
__device__ int    d_rowedges[EE];   // edge ids grouped by source
__device__ int    d_colsrc[EE];     // source node ids grouped by target
__device__ float  d_dinv[NN];
__device__ float  d_A[NN * 32];     // aggregated edge_attr per source node
__device__ float  d_h[NN * HH];     // node features fp32 (agg output / gemm input)
__device__ __half d_g[NN * HH];     // gemm output fp16, pre-scaled by dinv[n]
__device__ int    d_part[2 * NB];
__device__ int    d_partx[2 * NB];
// folded layer-1 weights: W @ Wg1
__device__ float d_Wn1[128 * 64];
__device__ float d_We1[32 * 64];
__device__ float d_bn1[64];
__device__ float d_be1[64];

#define FMA4(ACC, AV, B) \
    ACC.x = fmaf(AV, B.x, ACC.x); ACC.y = fmaf(AV, B.y, ACC.y); \
    ACC.z = fmaf(AV, B.z, ACC.z); ACC.w = fmaf(AV, B.w, ACC.w)

__device__ __forceinline__ void store_g_half4(int n, int col4, float4 o) {
    __half2 p0 = __floats2half2_rn(o.x, o.y);
    __half2 p1 = __floats2half2_rn(o.z, o.w);
    uint2 u;
    u.x = *(unsigned*)&p0;
    u.y = *(unsigned*)&p1;
    *(uint2*)&d_g[n * 64 + col4] = u;
}

// ---------------- fold: [Wn;We;bn;be] @ Wg1 (162 rows x 64) ----------------
__global__ void k_fold(const float* __restrict__ Wn, const float* __restrict__ We,
                       const float* __restrict__ bn, const float* __restrict__ be,
                       const float* __restrict__ Wg1) {
    __shared__ float sW[64 * 64];
    int t = threadIdx.x;  // 64 threads
    for (int i = t; i < 64 * 64; i += 64) sW[i] = Wg1[i];
    __syncthreads();
    int row = blockIdx.x;  // 0..161
    const float* src;
    float* dst;
    if (row < 128)      { src = &Wn[row * 64];          dst = &d_Wn1[row * 64]; }
    else if (row < 160) { src = &We[(row - 128) * 64];  dst = &d_We1[(row - 128) * 64]; }
    else if (row == 160){ src = bn;                     dst = d_bn1; }
    else                { src = be;                     dst = d_be1; }
    float acc = 0.0f;
#pragma unroll 16
    for (int k = 0; k < 64; k++) acc = fmaf(src[k], sW[k * 64 + t], acc);
    dst[t] = acc;
}

// ---------------- degree histograms ----------------
__global__ void k_zero() {
    int i = blockIdx.x * blockDim.x + threadIdx.x;
    int s = gridDim.x * blockDim.x;
    for (; i < NN; i += s) { d_deg_in[i] = 0; d_deg_out[i] = 0; }
}

// int4-batched: 4 edges per iteration, 8 independent atomics in flight
__global__ void k_count(const int* __restrict__ ei) {
    const int4* srcs = (const int4*)ei;
    const int4* dsts = (const int4*)(ei + EE);
    int i = blockIdx.x * blockDim.x + threadIdx.x;
    int s = gridDim.x * blockDim.x;
    for (; i < EE / 4; i += s) {
        int4 r = __ldg(&srcs[i]);
        int4 c = __ldg(&dsts[i]);
        atomicAdd(&d_deg_out[r.x], 1);
        atomicAdd(&d_deg_out[r.y], 1);
        atomicAdd(&d_deg_out[r.z], 1);
        atomicAdd(&d_deg_out[r.w], 1);
        atomicAdd(&d_deg_in[c.x], 1);
        atomicAdd(&d_deg_in[c.y], 1);
        atomicAdd(&d_deg_in[c.z], 1);
        atomicAdd(&d_deg_in[c.w], 1);
    }
}

// ===== 3-phase device-wide exclusive scan of both degree arrays ==============
__global__ void k_scanpart() {
    __shared__ int red[256];
    int b = blockIdx.x;
    const int* deg = (b < NB) ? d_deg_out : d_deg_in;
    int cb = (b < NB) ? b : b - NB;
    int base = cb * 1024 + threadIdx.x * 4;
    int s = 0;
#pragma unroll
    for (int i = 0; i < 4; i++) {
        int idx = base + i;
        if (idx < NN) s += deg[idx];
    }
    red[threadIdx.x] = s;
    __syncthreads();
    for (int off = 128; off; off >>= 1) {
        if (threadIdx.x < off) red[threadIdx.x] += red[threadIdx.x + off];
        __syncthreads();
    }
    if (threadIdx.x == 0) d_part[b] = red[0];
}

__global__ void k_scanmid() {
    __shared__ int sc[128];
    int a = blockIdx.x;            // 0 = row, 1 = col
    int t = threadIdx.x;
    int v = (t < NB) ? d_part[a * NB + t] : 0;
    sc[t] = v;
    __syncthreads();
    for (int off = 1; off < 128; off <<= 1) {
        int u = (t >= off) ? sc[t - off] : 0;
        __syncthreads();
        sc[t] += u;
        __syncthreads();
    }
    if (t < NB) d_partx[a * NB + t] = sc[t] - v;   // exclusive
    if (t == NB - 1) {
        if (a == 0) d_rowptr[NN] = sc[t];
        else        d_colptr[NN] = sc[t];
    }
}

__global__ void k_writeptr() {
    __shared__ int sc[1024];
    int b = blockIdx.x;
    int is_col = (b >= NB);
    const int* deg = is_col ? d_deg_in : d_deg_out;
    int* ptr = is_col ? d_colptr : d_rowptr;
    int* cur = is_col ? d_colcur : d_rowcur;
    int cb = is_col ? b - NB : b;
    int t = threadIdx.x;
    int i = cb * 1024 + t;
    int v = (i < NN) ? deg[i] : 0;
    sc[t] = v;
    __syncthreads();
    for (int off = 1; off < 1024; off <<= 1) {
        int u = (t >= off) ? sc[t - off] : 0;
        __syncthreads();
        sc[t] += u;
        __syncthreads();
    }
    if (i < NN) {
        int excl = sc[t] - v + d_partx[b];
        ptr[i] = excl;
        cur[i] = excl;
        if (is_col) d_dinv[i] = rsqrtf((float)(v + 1));
    }
}

// int4-batched scatter: 4 edges per iteration
__global__ void k_scatter(const int* __restrict__ ei) {
    const int4* srcs = (const int4*)ei;
    const int4* dsts = (const int4*)(ei + EE);
    int i = blockIdx.x * blockDim.x + threadIdx.x;
    int s = gridDim.x * blockDim.x;
    for (; i < EE / 4; i += s) {
        int4 r = __ldg(&srcs[i]);
        int4 c = __ldg(&dsts[i]);
        int e = i * 4;
        int p0 = atomicAdd(&d_rowcur[r.x], 1);
        int p1 = atomicAdd(&d_rowcur[r.y], 1);
        int p2 = atomicAdd(&d_rowcur[r.z], 1);
        int p3 = atomicAdd(&d_rowcur[r.w], 1);
        int q0 = atomicAdd(&d_colcur[c.x], 1);
        int q1 = atomicAdd(&d_colcur[c.y], 1);
        int q2 = atomicAdd(&d_colcur[c.z], 1);
        int q3 = atomicAdd(&d_colcur[c.w], 1);
        d_rowedges[p0] = e;
        d_rowedges[p1] = e + 1;
        d_rowedges[p2] = e + 2;
        d_rowedges[p3] = e + 3;
        d_colsrc[q0] = r.x;
        d_colsrc[q1] = r.y;
        d_colsrc[q2] = r.z;
        d_colsrc[q3] = r.w;
    }
}

// ------ A[n] = sum_{e: src=n} edge_attr[e]; 4 edges/warp-iter, float4 lanes ---
__global__ void k_aggattr(const float* __restrict__ ea) {
    int n = blockIdx.x * 8 + (threadIdx.x >> 5);
    int lane = threadIdx.x & 31;
    int grp = lane >> 3;        // 0..3: which edge of the 4-pack
    int gl  = lane & 7;         // 0..7: float4 column slot
    if (n >= NN) return;
    int beg = d_rowptr[n], end = d_rowptr[n + 1];
    float4 acc = make_float4(0.f, 0.f, 0.f, 0.f);
    for (int base = beg; base < end; base += 32) {
        int ev = (base + lane < end) ? d_rowedges[base + lane] : -1;
#pragma unroll
        for (int t = 0; t < 8; t++) {
            int e = __shfl_sync(FULL, ev, t * 4 + grp);
            if (e >= 0) {
                float4 v = *(const float4*)&ea[e * 32 + gl * 4];
                acc.x += v.x; acc.y += v.y; acc.z += v.z; acc.w += v.w;
            }
        }
    }
#pragma unroll
    for (int off = 8; off <= 16; off <<= 1) {
        acc.x += __shfl_xor_sync(FULL, acc.x, off);
        acc.y += __shfl_xor_sync(FULL, acc.y, off);
        acc.z += __shfl_xor_sync(FULL, acc.z, off);
        acc.w += __shfl_xor_sync(FULL, acc.w, off);
    }
    if (lane < 8) *(float4*)&d_A[n * 32 + gl * 4] = acc;
}

// === tiled SGEMM (layer-1 folded): g = dinv * (x@Wn1 + A@We1 + bn1 + deg*be1)
__global__ void k_gemm1(const float* __restrict__ x) {
    __shared__ float sA[32 * ASTRIDE];
    __shared__ float sB[32 * 64];
    int t = threadIdx.x;
    int nb = blockIdx.x * TILE_N;
    int tx = t >> 4, ty = t & 15;       // node group / col group
    int ln = t >> 1;                    // loader node 0..127
    int kh = (t & 1) * 16;              // loader k-offset
    int gn = nb + ln;

    float4 acc[8];
#pragma unroll
    for (int i = 0; i < 8; i++) acc[i] = make_float4(0.f, 0.f, 0.f, 0.f);

    for (int c = 0; c < 5; c++) {
        __syncthreads();
        const float4* Wv = (c < 4) ? (const float4*)(d_Wn1 + c * 2048)
                                   : (const float4*)d_We1;
        ((float4*)sB)[t]       = Wv[t];
        ((float4*)sB)[t + 256] = Wv[t + 256];

        float4 v[4];
#pragma unroll
        for (int i = 0; i < 4; i++) {
            if (gn < NN) {
                v[i] = (c < 4) ? *(const float4*)&x[gn * 128 + c * 32 + kh + 4 * i]
                               : *(const float4*)&d_A[gn * 32 + kh + 4 * i];
            } else v[i] = make_float4(0.f, 0.f, 0.f, 0.f);
        }
#pragma unroll
        for (int i = 0; i < 4; i++) {
            sA[(kh + 4 * i + 0) * ASTRIDE + ln] = v[i].x;
            sA[(kh + 4 * i + 1) * ASTRIDE + ln] = v[i].y;
            sA[(kh + 4 * i + 2) * ASTRIDE + ln] = v[i].z;
            sA[(kh + 4 * i + 3) * ASTRIDE + ln] = v[i].w;
        }
        __syncthreads();
#pragma unroll 8
        for (int k = 0; k < 32; k++) {
            float4 a0 = *(const float4*)&sA[k * ASTRIDE + tx * 8];
            float4 a1 = *(const float4*)&sA[k * ASTRIDE + tx * 8 + 4];
            float4 b  = *(const float4*)&sB[k * 64 + ty * 4];
            FMA4(acc[0], a0.x, b); FMA4(acc[1], a0.y, b);
            FMA4(acc[2], a0.z, b); FMA4(acc[3], a0.w, b);
            FMA4(acc[4], a1.x, b); FMA4(acc[5], a1.y, b);
            FMA4(acc[6], a1.z, b); FMA4(acc[7], a1.w, b);
        }
    }
    float4 bnv = *(const float4*)&d_bn1[ty * 4];
    float4 bev = *(const float4*)&d_be1[ty * 4];
    int nrow = nb + tx * 8;
#pragma unroll
    for (int i = 0; i < 8; i++) {
        int n = nrow + i;
        if (n < NN) {
            float dg = (float)d_deg_out[n];
            float sc = d_dinv[n];
            float4 o;
            o.x = sc * (acc[i].x + bnv.x + dg * bev.x);
            o.y = sc * (acc[i].y + bnv.y + dg * bev.y);
            o.z = sc * (acc[i].z + bnv.z + dg * bev.z);
            o.w = sc * (acc[i].w + bnv.w + dg * bev.w);
            store_g_half4(n, ty * 4, o);
        }
    }
}

// ====== tiled SGEMM: g[n] = dinv[n] * (h[n] @ W)  (64x64), fp16 out ==========
__global__ void k_gemm64(const float* __restrict__ W) {
    __shared__ float sA[32 * ASTRIDE];
    __shared__ float sB[32 * 64];
    int t = threadIdx.x;
    int nb = blockIdx.x * TILE_N;
    int tx = t >> 4, ty = t & 15;
    int ln = t >> 1;
    int kh = (t & 1) * 16;
    int gn = nb + ln;

    float4 acc[8];
#pragma unroll
    for (int i = 0; i < 8; i++) acc[i] = make_float4(0.f, 0.f, 0.f, 0.f);

    for (int c = 0; c < 2; c++) {
        __syncthreads();
        const float4* Wv = (const float4*)(W + c * 2048);
        ((float4*)sB)[t]       = Wv[t];
        ((float4*)sB)[t + 256] = Wv[t + 256];

        float4 v[4];
#pragma unroll
        for (int i = 0; i < 4; i++)
            v[i] = (gn < NN) ? *(const float4*)&d_h[gn * 64 + c * 32 + kh + 4 * i]
                             : make_float4(0.f, 0.f, 0.f, 0.f);
#pragma unroll
        for (int i = 0; i < 4; i++) {
            sA[(kh + 4 * i + 0) * ASTRIDE + ln] = v[i].x;
            sA[(kh + 4 * i + 1) * ASTRIDE + ln] = v[i].y;
            sA[(kh + 4 * i + 2) * ASTRIDE + ln] = v[i].z;
            sA[(kh + 4 * i + 3) * ASTRIDE + ln] = v[i].w;
        }
        __syncthreads();
#pragma unroll 8
        for (int k = 0; k < 32; k++) {
            float4 a0 = *(const float4*)&sA[k * ASTRIDE + tx * 8];
            float4 a1 = *(const float4*)&sA[k * ASTRIDE + tx * 8 + 4];
            float4 b  = *(const float4*)&sB[k * 64 + ty * 4];
            FMA4(acc[0], a0.x, b); FMA4(acc[1], a0.y, b);
            FMA4(acc[2], a0.z, b); FMA4(acc[3], a0.w, b);
            FMA4(acc[4], a1.x, b); FMA4(acc[5], a1.y, b);
            FMA4(acc[6], a1.z, b); FMA4(acc[7], a1.w, b);
        }
    }
    int nrow = nb + tx * 8;
#pragma unroll
    for (int i = 0; i < 8; i++) {
        int n = nrow + i;
        if (n < NN) {
            float sc = d_dinv[n];
            float4 o;
            o.x = sc * acc[i].x; o.y = sc * acc[i].y;
            o.z = sc * acc[i].z; o.w = sc * acc[i].w;
            store_g_half4(n, ty * 4, o);
        }
    }
}

// --- h[c] = act( dinv[c]*(sum g[s] + g[c]) + b ); 2 nodes/warp, fp16 gathers --
__global__ void k_agg(const float* __restrict__ bias, int do_relu) {
    int warp = threadIdx.x >> 5;
    int lane = threadIdx.x & 31;
    int half = lane >> 4;                // 0 or 1: which node
    int hl   = lane & 15;                // 0..15: 4-col slot
    int n = blockIdx.x * 16 + warp * 2 + half;
    if (n >= NN) return;
    unsigned hmask = half ? 0xFFFF0000u : 0x0000FFFFu;
    int beg = d_colptr[n], end = d_colptr[n + 1];
    // self loop
    uint2 sr = *(const uint2*)&d_g[n * 64 + hl * 4];
    float2 sf0 = __half22float2(*(__half2*)&sr.x);
    float2 sf1 = __half22float2(*(__half2*)&sr.y);
    float4 acc = make_float4(sf0.x, sf0.y, sf1.x, sf1.y);
    for (int base = beg; base < end; base += 16) {
        int cnt = min(16, end - base);
        int sv = (base + hl < end) ? d_colsrc[base + hl] : 0;
        for (int t = 0; t < cnt; t++) {
            int s = __shfl_sync(hmask, sv, (half << 4) + t);
            uint2 raw = __ldg((const uint2*)&d_g[s * 64 + hl * 4]);
            float2 f0 = __half22float2(*(__half2*)&raw.x);
            float2 f1 = __half22float2(*(__half2*)&raw.y);
            acc.x += f0.x; acc.y += f0.y; acc.z += f1.x; acc.w += f1.y;
        }
    }
    float sc = d_dinv[n];
    float4 b = *(const float4*)&bias[hl * 4];
    float4 o;
    o.x = fmaf(sc, acc.x, b.x);
    o.y = fmaf(sc, acc.y, b.y);
    o.z = fmaf(sc, acc.z, b.z);
    o.w = fmaf(sc, acc.w, b.w);
    if (do_relu) {
        o.x = fmaxf(o.x, 0.0f); o.y = fmaxf(o.y, 0.0f);
        o.z = fmaxf(o.z, 0.0f); o.w = fmaxf(o.w, 0.0f);
    }
    *(float4*)&d_h[n * 64 + hl * 4] = o;
}

// ---------------- mean pool (sorted batch) + classifier ----------------
__device__ __forceinline__ int lbound(const int* a, int n, int v) {
    int lo = 0, hi = n;
    while (lo < hi) {
        int mid = (lo + hi) >> 1;
        if (a[mid] < v) lo = mid + 1; else hi = mid;
    }
    return lo;
}

__global__ void k_classifier(const int* __restrict__ batch,
                             const float* __restrict__ Wc1, const float* __restrict__ bc1,
                             const float* __restrict__ Wc2, const float* __restrict__ bc2,
                             float* __restrict__ out) {
    int g = blockIdx.x * 8 + (threadIdx.x >> 5);
    int lane = threadIdx.x & 31;
    if (g >= GG) return;
    int lo = 0, hi = 0;
    if (lane == 0) {
        lo = lbound(batch, NN, g);
        hi = lbound(batch, NN, g + 1);
    }
    lo = __shfl_sync(FULL, lo, 0);
    hi = __shfl_sync(FULL, hi, 0);
    float2 s = make_float2(0.0f, 0.0f);
    for (int n = lo; n < hi; n++) {
        float2 v = *(const float2*)&d_h[n * 64 + 2 * lane];
        s.x += v.x; s.y += v.y;
    }
    float cnt = (float)(hi - lo);
    float inv = (cnt > 0.0f) ? 1.0f / cnt : 0.0f;
    float m0 = s.x * inv, m1 = s.y * inv;  // cols 2*lane, 2*lane+1
    float hid = bc1[lane];
#pragma unroll
    for (int k = 0; k < 64; k++) {
        float src = (k & 1) ? m1 : m0;
        float mk = __shfl_sync(FULL, src, k >> 1);
        hid = fmaf(mk, Wc1[k * 32 + lane], hid);
    }
    hid = fmaxf(hid, 0.0f);
    float v = hid * Wc2[lane];
#pragma unroll
    for (int off = 16; off; off >>= 1) v += __shfl_xor_sync(FULL, v, off);
    if (lane == 0) out[g] = v + bc2[0];
}

// ---------------- launch ----------------
extern "C" void kernel_launch(void* const* d_in, const int* in_sizes, int n_in,
                              void* d_out, int out_size) {
    const float* x    = (const float*)d_in[0];
    const int*   ei   = (const int*)  d_in[1];
    const float* ea   = (const float*)d_in[2];
    const int*   batch= (const int*)  d_in[3];
    const float* Wn   = (const float*)d_in[4];
    const float* bn   = (const float*)d_in[5];
    const float* We   = (const float*)d_in[6];
    const float* be   = (const float*)d_in[7];
    const float* Wg1  = (const float*)d_in[8];
    const float* bg1  = (const float*)d_in[9];
    const float* Wg2  = (const float*)d_in[10];
    const float* bg2  = (const float*)d_in[11];
    const float* Wg3  = (const float*)d_in[12];
    const float* bg3  = (const float*)d_in[13];
    const float* Wc1  = (const float*)d_in[14];
    const float* bc1  = (const float*)d_in[15];
    const float* Wc2  = (const float*)d_in[16];
    const float* bc2  = (const float*)d_in[17];
    float* out = (float*)d_out;

    const int WB  = (NN + 7) / 8;                  // warp-per-node blocks
    const int AB  = (NN + 15) / 16;                // 2-nodes-per-warp blocks
    const int GB  = (NN + TILE_N - 1) / TILE_N;    // gemm tiles

    k_fold<<<162, 64>>>(Wn, We, bn, be, Wg1);
    k_zero<<<256, 256>>>();
    k_count<<<512, 256>>>(ei);
    k_scanpart<<<2 * NB, 256>>>();
    k_scanmid<<<2, 128>>>();
    k_writeptr<<<2 * NB, 1024>>>();
    k_scatter<<<512, 256>>>(ei);
    k_aggattr<<<WB, 256>>>(ea);
    k_gemm1<<<GB, 256>>>(x);                       // emits layer-1 g (fp16)

    k_agg<<<AB, 256>>>(bg1, 1);
    k_gemm64<<<GB, 256>>>(Wg2);
    k_agg<<<AB, 256>>>(bg2, 1);
    k_gemm64<<<GB, 256>>>(Wg3);
    k_agg<<<AB, 256>>>(bg3, 0);

    k_classifier<<<64, 256>>>(batch, Wc1, bc1, Wc2, bc2, out);
}